// round 2
// baseline (speedup 1.0000x reference)
#include <cuda_runtime.h>
#include <cstdint>

#define HDIM 4096
#define TPB  256
#define V4_PER_THREAD (HDIM / (TPB * 4))   // 4 float4 per thread

__global__ __launch_bounds__(TPB, 8)
void quant_int4_kernel(const float* __restrict__ x,
                       float* __restrict__ packed_out,   // packed int8 VALUES as fp32
                       float* __restrict__ scales_out)
{
    const int row = blockIdx.x;
    const int t   = threadIdx.x;

    const float4* __restrict__ xrow =
        reinterpret_cast<const float4*>(x + (size_t)row * HDIM);

    // ---- pass 1: load 16 elements into registers, local absmax ----
    float4 v[V4_PER_THREAD];
    float amax = 0.0f;
#pragma unroll
    for (int i = 0; i < V4_PER_THREAD; i++) {
        v[i] = xrow[i * TPB + t];
        amax = fmaxf(amax, fmaxf(fmaxf(fabsf(v[i].x), fabsf(v[i].y)),
                                 fmaxf(fabsf(v[i].z), fabsf(v[i].w))));
    }

    // ---- warp reduction ----
#pragma unroll
    for (int o = 16; o > 0; o >>= 1)
        amax = fmaxf(amax, __shfl_xor_sync(0xffffffffu, amax, o));

    // ---- cross-warp reduction (8 warps) ----
    __shared__ float smax[TPB / 32];
    if ((t & 31) == 0) smax[t >> 5] = amax;
    __syncthreads();

    float rmax = smax[0];
#pragma unroll
    for (int w = 1; w < TPB / 32; w++) rmax = fmaxf(rmax, smax[w]);

    const float scale = fmaxf(rmax * (0.9f / 7.0f), 1e-8f);
    const float inv   = 1.0f / scale;

    if (t == 0) scales_out[row] = scale;

    // ---- pass 2: quantize from registers, pack 2 nibbles -> int8 value -> fp32 ----
    // Each float4 -> 4 int4 -> 2 packed bytes -> 2 output floats (one float2 store).
    float2* __restrict__ orow =
        reinterpret_cast<float2*>(packed_out + (size_t)row * (HDIM / 2));

#pragma unroll
    for (int i = 0; i < V4_PER_THREAD; i++) {
        int q0 = __float2int_rn(v[i].x * inv);
        int q1 = __float2int_rn(v[i].y * inv);
        int q2 = __float2int_rn(v[i].z * inv);
        int q3 = __float2int_rn(v[i].w * inv);
        q0 = max(-8, min(7, q0));
        q1 = max(-8, min(7, q1));
        q2 = max(-8, min(7, q2));
        q3 = max(-8, min(7, q3));
        // element 0 -> low nibble, element 1 -> high nibble; byte is SIGNED int8
        int8_t b0 = (int8_t)(uint8_t)((q0 & 0xF) | ((q1 & 0xF) << 4));
        int8_t b1 = (int8_t)(uint8_t)((q2 & 0xF) | ((q3 & 0xF) << 4));
        float2 o;
        o.x = (float)b0;
        o.y = (float)b1;
        orow[i * TPB + t] = o;
    }
}

extern "C" void kernel_launch(void* const* d_in, const int* in_sizes, int n_in,
                              void* d_out, int out_size)
{
    const float* x = (const float*)d_in[0];
    const int n_elems = in_sizes[0];              // 4*2048*4096
    const int rows    = n_elems / HDIM;           // 8192

    float* packed = (float*)d_out;                         // [rows, 2048] as fp32
    float* scales = (float*)d_out + (size_t)rows * (HDIM / 2);  // [rows] fp32

    quant_int4_kernel<<<rows, TPB>>>(x, packed, scales);
}